// round 1
// baseline (speedup 1.0000x reference)
#include <cuda_runtime.h>

#define S_LEN   2048
#define D_MODEL 1024
#define NHEADS  16
#define HDIM    64
#define NB      2

// Scratch (allocation-free rule: static __device__ arrays)
__device__ float g_q[NB * NHEADS * S_LEN * HDIM];
__device__ float g_k[NB * NHEADS * S_LEN * HDIM];
__device__ float g_v[NB * NHEADS * S_LEN * HDIM];
__device__ float g_att[NB * S_LEN * D_MODEL];

// ---------------------------------------------------------------------------
// Kernel 1: y = x @ W^T for W in {Wq, Wk, Wv}; output stored as [b, h, s, hd]
// 64x64 output tile per CTA, k-chunks of 16, 256 threads, 4x4 per thread.
// ---------------------------------------------------------------------------
__global__ __launch_bounds__(256) void qkv_gemm_kernel(
    const float* __restrict__ x,
    const float* __restrict__ Wq,
    const float* __restrict__ Wk,
    const float* __restrict__ Wv)
{
    __shared__ float xs[16][68];  // [kk][row], padded
    __shared__ float ws[16][68];

    const float* W   = (blockIdx.z == 0) ? Wq : (blockIdx.z == 1) ? Wk : Wv;
    float*       out = (blockIdx.z == 0) ? g_q : (blockIdx.z == 1) ? g_k : g_v;

    const int m0  = blockIdx.x * 64;   // column tile (head dim block): head = blockIdx.x
    const int n0  = blockIdx.y * 64;   // row tile (b*S + s)
    const int tid = threadIdx.x;
    const int lrow = tid >> 2;         // 0..63
    const int kq   = tid & 3;          // 0..3
    const int tr   = tid >> 4;         // 0..15
    const int tc   = tid & 15;         // 0..15

    float acc[4][4];
#pragma unroll
    for (int i = 0; i < 4; i++)
#pragma unroll
        for (int j = 0; j < 4; j++) acc[i][j] = 0.0f;

    const float* xg = x + (size_t)(n0 + lrow) * D_MODEL + kq * 4;
    const float* wg = W + (size_t)(m0 + lrow) * D_MODEL + kq * 4;

    for (int k0 = 0; k0 < D_MODEL; k0 += 16) {
        float4 xv = *(const float4*)(xg + k0);
        float4 wv = *(const float4*)(wg + k0);
        __syncthreads();
        xs[kq * 4 + 0][lrow] = xv.x;
        xs[kq * 4 + 1][lrow] = xv.y;
        xs[kq * 4 + 2][lrow] = xv.z;
        xs[kq * 4 + 3][lrow] = xv.w;
        ws[kq * 4 + 0][lrow] = wv.x;
        ws[kq * 4 + 1][lrow] = wv.y;
        ws[kq * 4 + 2][lrow] = wv.z;
        ws[kq * 4 + 3][lrow] = wv.w;
        __syncthreads();
#pragma unroll
        for (int kk = 0; kk < 16; kk++) {
            float4 a4 = *(const float4*)&xs[kk][tr * 4];
            float4 b4 = *(const float4*)&ws[kk][tc * 4];
            float a[4] = {a4.x, a4.y, a4.z, a4.w};
            float b[4] = {b4.x, b4.y, b4.z, b4.w};
#pragma unroll
            for (int i = 0; i < 4; i++)
#pragma unroll
                for (int j = 0; j < 4; j++) acc[i][j] += a[i] * b[j];
        }
    }

    const int head = blockIdx.x;
#pragma unroll
    for (int i = 0; i < 4; i++) {
        int n  = n0 + tr * 4 + i;
        int bb = n >> 11;               // n / S_LEN
        int s  = n & (S_LEN - 1);
        float4 ov = make_float4(acc[i][0], acc[i][1], acc[i][2], acc[i][3]);
        *(float4*)&out[(((size_t)(bb * NHEADS + head) * S_LEN) + s) * HDIM + tc * 4] = ov;
    }
}

// ---------------------------------------------------------------------------
// Kernel 2: flash attention with relative-position skew, fused per (b,h).
// CTA: 64 query rows, 256 threads (8 warps x 8 rows), loop over 32 KV tiles.
//   Srel[s,t]: d = t-s;  d<=0 -> q[s]  . Er[S-1+d]
//              d==1 -> 0  (Er slot zero-filled)
//              d>=2 -> q[s+1]. Er[d-2]
// smem strides of 65 give conflict-free lane-indexed access.
// ---------------------------------------------------------------------------
#define SQ_OFF   0
#define SK_OFF   (65 * 65)
#define SV_OFF   (SK_OFF + 64 * 65)
#define SER_OFF  (SV_OFF + 64 * 65)
#define SP_OFF   (SER_OFF + 128 * 65)
#define SMEM_FLOATS (SP_OFF + 64 * 65)
#define SMEM_BYTES  (SMEM_FLOATS * 4)

__global__ __launch_bounds__(256) void attn_kernel(const float* __restrict__ Er)
{
    extern __shared__ float sm[];
    float* sq  = sm + SQ_OFF;    // [65][65] rows s0..s0+64 (row 64 for the s+1 case)
    float* sk  = sm + SK_OFF;    // [64][65]
    float* sv  = sm + SV_OFF;    // [64][65]
    float* ser = sm + SER_OFF;   // [128][65], indexed by di = d - dlo
    float* sp  = sm + SP_OFF;    // [64][65] probability tile

    const int tid  = threadIdx.x;
    const int lane = tid & 31;
    const int wr   = tid >> 5;        // warp 0..7
    const int rl0  = wr * 8;          // first local row of this warp
    const int s0   = blockIdx.x * 64;
    const int bh   = blockIdx.y;      // b*NHEADS + h

    const float* qb = g_q + (size_t)bh * S_LEN * HDIM;
    const float* kb = g_k + (size_t)bh * S_LEN * HDIM;
    const float* vb = g_v + (size_t)bh * S_LEN * HDIM;

    // Load Q tile: rows s0 .. s0+64 (65 rows; row 64 only used via d>=2, which
    // never happens for the last sequence row, so zero-fill when out of range).
    for (int i4 = tid; i4 < 65 * 16; i4 += 256) {
        int r  = i4 >> 4;
        int kq = i4 & 15;
        float4 v = make_float4(0.f, 0.f, 0.f, 0.f);
        if (s0 + r < S_LEN) v = *(const float4*)&qb[(size_t)(s0 + r) * HDIM + kq * 4];
        float* dst = &sq[r * 65 + kq * 4];
        dst[0] = v.x; dst[1] = v.y; dst[2] = v.z; dst[3] = v.w;
    }

    float m_i[8], l_i[8], o_i[8][2];
#pragma unroll
    for (int r = 0; r < 8; r++) {
        m_i[r] = -1e30f; l_i[r] = 0.0f; o_i[r][0] = 0.0f; o_i[r][1] = 0.0f;
    }

    const float scale = 0.03125f;  // D^-0.5 = 1/32

    for (int t0 = 0; t0 < S_LEN; t0 += 64) {
        __syncthreads();  // previous tile fully consumed

        // K and V tiles
        for (int i4 = tid; i4 < 64 * 16; i4 += 256) {
            int c  = i4 >> 4;
            int kq = i4 & 15;
            float4 kv = *(const float4*)&kb[(size_t)(t0 + c) * HDIM + kq * 4];
            float* d1 = &sk[c * 65 + kq * 4];
            d1[0] = kv.x; d1[1] = kv.y; d1[2] = kv.z; d1[3] = kv.w;
            float4 vv = *(const float4*)&vb[(size_t)(t0 + c) * HDIM + kq * 4];
            float* d2 = &sv[c * 65 + kq * 4];
            d2[0] = vv.x; d2[1] = vv.y; d2[2] = vv.z; d2[3] = vv.w;
        }

        // Er window for this tile: di in [0,128), d = dlo + di
        const int dlo = t0 - s0 - 63;
        for (int i4 = tid; i4 < 128 * 16; i4 += 256) {
            int di = i4 >> 4;
            int kq = i4 & 15;
            int d  = dlo + di;
            int j  = (d <= 0) ? (S_LEN - 1 + d) : (d - 2);  // d==1 -> j=-1 -> zero
            float4 ev = make_float4(0.f, 0.f, 0.f, 0.f);
            if (j >= 0 && j < S_LEN) ev = *(const float4*)&Er[(size_t)j * HDIM + kq * 4];
            float* d3 = &ser[di * 65 + kq * 4];
            d3[0] = ev.x; d3[1] = ev.y; d3[2] = ev.z; d3[3] = ev.w;
        }
        __syncthreads();

        // Selectors: does rel use q[s] or q[s+1]?  (constant per (r,cc) per tile)
        bool un[8][2];
#pragma unroll
        for (int r = 0; r < 8; r++) {
#pragma unroll
            for (int cc = 0; cc < 2; cc++) {
                int c = cc * 32 + lane;
                un[r][cc] = ((t0 + c) - (s0 + rl0 + r)) >= 2;
            }
        }

        float aqk[8][2], arl[8][2];
#pragma unroll
        for (int r = 0; r < 8; r++) {
            aqk[r][0] = 0.f; aqk[r][1] = 0.f; arl[r][0] = 0.f; arl[r][1] = 0.f;
        }

#pragma unroll 4
        for (int kk = 0; kk < HDIM; kk++) {
            float k0 = sk[lane * 65 + kk];
            float k1 = sk[(lane + 32) * 65 + kk];
            float qv[9];
#pragma unroll
            for (int r = 0; r < 9; r++) qv[r] = sq[(rl0 + r) * 65 + kk];
#pragma unroll
            for (int r = 0; r < 8; r++) {
                int diA = lane + 63 - (rl0 + r);
                float e0 = ser[diA * 65 + kk];
                float e1 = ser[(diA + 32) * 65 + kk];
                aqk[r][0] += qv[r] * k0;
                aqk[r][1] += qv[r] * k1;
                arl[r][0] += (un[r][0] ? qv[r + 1] : qv[r]) * e0;
                arl[r][1] += (un[r][1] ? qv[r + 1] : qv[r]) * e1;
            }
        }

        // Online softmax update per row
#pragma unroll
        for (int r = 0; r < 8; r++) {
            float sc0 = (aqk[r][0] + arl[r][0]) * scale;
            float sc1 = (aqk[r][1] + arl[r][1]) * scale;
            float mx = fmaxf(sc0, sc1);
#pragma unroll
            for (int off = 16; off; off >>= 1)
                mx = fmaxf(mx, __shfl_xor_sync(0xffffffffu, mx, off));
            float mnew = fmaxf(m_i[r], mx);
            float p0 = __expf(sc0 - mnew);
            float p1 = __expf(sc1 - mnew);
            float ps = p0 + p1;
#pragma unroll
            for (int off = 16; off; off >>= 1)
                ps += __shfl_xor_sync(0xffffffffu, ps, off);
            float f = __expf(m_i[r] - mnew);
            l_i[r]  = l_i[r] * f + ps;
            m_i[r]  = mnew;
            o_i[r][0] *= f;
            o_i[r][1] *= f;
            sp[(rl0 + r) * 65 + lane]      = p0;
            sp[(rl0 + r) * 65 + lane + 32] = p1;
        }
        __syncwarp();

        // O += P @ V  (lane owns output dims lane and lane+32)
#pragma unroll 4
        for (int t = 0; t < 64; t++) {
            float v0 = sv[t * 65 + lane];
            float v1 = sv[t * 65 + lane + 32];
#pragma unroll
            for (int r = 0; r < 8; r++) {
                float pv = sp[(rl0 + r) * 65 + t];
                o_i[r][0] += pv * v0;
                o_i[r][1] += pv * v1;
            }
        }
    }

    // Epilogue: normalize, write to [b, s, h*64 + dd]
    const int b = bh >> 4;
    const int h = bh & 15;
#pragma unroll
    for (int r = 0; r < 8; r++) {
        int s = s0 + rl0 + r;
        float inv = 1.0f / l_i[r];
        float* op = &g_att[((size_t)(b * S_LEN + s)) * D_MODEL + h * HDIM];
        op[lane]      = o_i[r][0] * inv;
        op[lane + 32] = o_i[r][1] * inv;
    }
}

// ---------------------------------------------------------------------------
// Kernel 3: LayerNorm over last dim (1024), one 256-thread block per row.
// ---------------------------------------------------------------------------
__global__ __launch_bounds__(256) void ln_kernel(
    const float* __restrict__ lw, const float* __restrict__ lb,
    float* __restrict__ out)
{
    __shared__ float red[16];
    const int row = blockIdx.x;
    const int tid = threadIdx.x;
    const float* xr = g_att + (size_t)row * D_MODEL;

    float4 v = *(const float4*)&xr[tid * 4];
    float sum = v.x + v.y + v.z + v.w;
    float ss  = fmaf(v.x, v.x, fmaf(v.y, v.y, fmaf(v.z, v.z, v.w * v.w)));
#pragma unroll
    for (int off = 16; off; off >>= 1) {
        sum += __shfl_xor_sync(0xffffffffu, sum, off);
        ss  += __shfl_xor_sync(0xffffffffu, ss, off);
    }
    if ((tid & 31) == 0) {
        red[tid >> 5]     = sum;
        red[8 + (tid >> 5)] = ss;
    }
    __syncthreads();
    float ts = 0.f, tq = 0.f;
#pragma unroll
    for (int w = 0; w < 8; w++) { ts += red[w]; tq += red[8 + w]; }
    float mu  = ts * (1.0f / D_MODEL);
    float var = tq * (1.0f / D_MODEL) - mu * mu;
    float rs  = rsqrtf(var + 1e-5f);

    float4 w4 = *(const float4*)&lw[tid * 4];
    float4 b4 = *(const float4*)&lb[tid * 4];
    float4 o;
    o.x = (v.x - mu) * rs * w4.x + b4.x;
    o.y = (v.y - mu) * rs * w4.y + b4.y;
    o.z = (v.z - mu) * rs * w4.z + b4.z;
    o.w = (v.w - mu) * rs * w4.w + b4.w;
    *(float4*)&out[(size_t)row * D_MODEL + tid * 4] = o;
}

// ---------------------------------------------------------------------------
extern "C" void kernel_launch(void* const* d_in, const int* in_sizes, int n_in,
                              void* d_out, int out_size)
{
    (void)in_sizes; (void)n_in; (void)out_size;
    const float* x  = (const float*)d_in[0];
    const float* Wq = (const float*)d_in[1];
    const float* Wk = (const float*)d_in[2];
    const float* Wv = (const float*)d_in[3];
    const float* Er = (const float*)d_in[4];
    const float* lw = (const float*)d_in[5];
    const float* lb = (const float*)d_in[6];
    float* out = (float*)d_out;

    qkv_gemm_kernel<<<dim3(16, 64, 3), 256>>>(x, Wq, Wk, Wv);

    cudaFuncSetAttribute(attn_kernel,
                         cudaFuncAttributeMaxDynamicSharedMemorySize, SMEM_BYTES);
    attn_kernel<<<dim3(S_LEN / 64, NB * NHEADS), 256, SMEM_BYTES>>>(Er);

    ln_kernel<<<NB * S_LEN, 256>>>(lw, lb, out);
}

// round 3
// speedup vs baseline: 1.1583x; 1.1583x over previous
#include <cuda_runtime.h>
#include <cuda_bf16.h>
#include <cstdint>

#define S_LEN   2048
#define D_MODEL 1024
#define NHEADS  16
#define HDIM    64
#define NB      2

// Scratch (allocation-free rule: static __device__ arrays)
__device__ float g_q[NB * NHEADS * S_LEN * HDIM];
__device__ float g_k[NB * NHEADS * S_LEN * HDIM];
__device__ float g_v[NB * NHEADS * S_LEN * HDIM];
__device__ float g_att[NB * S_LEN * D_MODEL];

// bf16 split copies of x and W (hi + lo)
__device__ __nv_bfloat16 g_xhi[NB * S_LEN * D_MODEL];
__device__ __nv_bfloat16 g_xlo[NB * S_LEN * D_MODEL];
__device__ __nv_bfloat16 g_whi[3 * D_MODEL * D_MODEL];
__device__ __nv_bfloat16 g_wlo[3 * D_MODEL * D_MODEL];

// ===========================================================================
// HMMA helpers (valid on base sm_100: no tcgen05, no 'a' features)
// ===========================================================================
__device__ __forceinline__ uint32_t smem_u32(const void* p) {
    uint32_t a;
    asm("{ .reg .u64 t; cvta.to.shared.u64 t, %1; cvt.u32.u64 %0, t; }"
        : "=r"(a) : "l"(p));
    return a;
}

__device__ __forceinline__ void ldsm4(uint32_t addr, uint32_t* r) {
    asm volatile("ldmatrix.sync.aligned.m8n8.x4.shared.b16 {%0,%1,%2,%3}, [%4];"
                 : "=r"(r[0]), "=r"(r[1]), "=r"(r[2]), "=r"(r[3]) : "r"(addr));
}

__device__ __forceinline__ void mma16816(float* d, const uint32_t* a,
                                         uint32_t b0, uint32_t b1) {
    asm volatile(
        "mma.sync.aligned.m16n8k16.row.col.f32.bf16.bf16.f32 "
        "{%0,%1,%2,%3}, {%4,%5,%6,%7}, {%8,%9}, {%0,%1,%2,%3};"
        : "+f"(d[0]), "+f"(d[1]), "+f"(d[2]), "+f"(d[3])
        : "r"(a[0]), "r"(a[1]), "r"(a[2]), "r"(a[3]), "r"(b0), "r"(b1));
}

#define SWZ128(off) ((off) ^ (((off) >> 3) & 0x70))

// ===========================================================================
// Kernel 0: split fp32 x / W into bf16 hi + lo pairs
// ===========================================================================
#define X_ELEMS (NB * S_LEN * D_MODEL)          // 4 M
#define W_ELEMS (3 * D_MODEL * D_MODEL)         // 3 M
#define SPLIT_QUADS ((X_ELEMS + W_ELEMS) / 4)   // 1.75 M

__global__ __launch_bounds__(256) void split_kernel(
    const float* __restrict__ x,
    const float* __restrict__ Wq,
    const float* __restrict__ Wk,
    const float* __restrict__ Wv)
{
    int gid = blockIdx.x * 256 + threadIdx.x;
    if (gid >= SPLIT_QUADS) return;
    int e4 = gid * 4;
    const float* src;
    __nv_bfloat16 *dh, *dl;
    if (e4 < X_ELEMS) {
        src = x + e4; dh = g_xhi + e4; dl = g_xlo + e4;
    } else {
        int j = e4 - X_ELEMS;
        int w = j >> 20;                  // 0..2 (1M elems per W)
        int o = j & ((1 << 20) - 1);
        src = (w == 0 ? Wq : w == 1 ? Wk : Wv) + o;
        dh = g_whi + j; dl = g_wlo + j;
    }
    float4 v = *(const float4*)src;
    __nv_bfloat16 h0 = __float2bfloat16(v.x);
    __nv_bfloat16 h1 = __float2bfloat16(v.y);
    __nv_bfloat16 h2 = __float2bfloat16(v.z);
    __nv_bfloat16 h3 = __float2bfloat16(v.w);
    __nv_bfloat16 l0 = __float2bfloat16(v.x - __bfloat162float(h0));
    __nv_bfloat16 l1 = __float2bfloat16(v.y - __bfloat162float(h1));
    __nv_bfloat16 l2 = __float2bfloat16(v.z - __bfloat162float(h2));
    __nv_bfloat16 l3 = __float2bfloat16(v.w - __bfloat162float(h3));
    *(__nv_bfloat162*)&dh[0] = __nv_bfloat162(h0, h1);
    *(__nv_bfloat162*)&dh[2] = __nv_bfloat162(h2, h3);
    *(__nv_bfloat162*)&dl[0] = __nv_bfloat162(l0, l1);
    *(__nv_bfloat162*)&dl[2] = __nv_bfloat162(l2, l3);
}

// ===========================================================================
// Kernel 1: HMMA QKV GEMM, bf16 2-split (hi*hi + hi*lo + lo*hi)
// CTA: 128 x-rows (M) x 128 features (N); K chunks of 64; 8 warps (2m x 4n),
// warp tile 64x32 = 4 m-tiles(16) x 4 n-tiles(8).
// Output written to g_q/g_k/g_v in [b, h, s, hd] layout (fp32).
// ===========================================================================
#define GK_CHUNK   64
#define GK_CHUNKS  (D_MODEL / GK_CHUNK)    // 16
#define TILE_BYTES (128 * 128)             // 128 rows x 128B (64 bf16)

#define SO_XHI     0
#define SO_XLO     (SO_XHI + TILE_BYTES)
#define SO_WHI     (SO_XLO + TILE_BYTES)
#define SO_WLO     (SO_WHI + TILE_BYTES)
#define GEMM_SMEM_BYTES (128 * 132 * 4)    // 67584 (>= 4*16384 tile bytes)

__global__ __launch_bounds__(256) void qkv_mma_kernel()
{
    extern __shared__ char sm[];
    const uint32_t smem_base = smem_u32(sm);
    const int tid  = threadIdx.x;
    const int wid  = tid >> 5;
    const int lane = tid & 31;
    const int wm   = wid & 1;             // m half (64 rows)
    const int wn   = wid >> 1;            // n quarter (32 features)

    const int fc = blockIdx.x;            // feature tile 0..7
    const int rt = blockIdx.y;            // row tile 0..31
    const int w  = blockIdx.z;            // 0..2
    const int n0 = rt * 128;              // x-row base
    const int m0 = fc * 128;              // feature base

    const __nv_bfloat16* Xh = g_xhi;
    const __nv_bfloat16* Xl = g_xlo;
    const __nv_bfloat16* Wh = g_whi + (size_t)w * D_MODEL * D_MODEL;
    const __nv_bfloat16* Wl = g_wlo + (size_t)w * D_MODEL * D_MODEL;
    float* out = (w == 0) ? g_q : (w == 1) ? g_k : g_v;

    float acc[4][4][4];
#pragma unroll
    for (int mt = 0; mt < 4; mt++)
#pragma unroll
        for (int nt = 0; nt < 4; nt++)
#pragma unroll
            for (int i = 0; i < 4; i++) acc[mt][nt][i] = 0.0f;

    // ldmatrix source addresses (fixed per thread, add tile offsets)
    const int a_row = wm * 64 + (lane & 15);
    const int a_kq  = (lane >> 4) * 8;                       // 0 or 8
    const int b_row = wn * 32 + (lane & 7) + (lane >> 4) * 8;
    const int b_kq  = ((lane >> 3) & 1) * 8;                 // 0 or 8

    for (int ch = 0; ch < GK_CHUNKS; ch++) {
        const int k0 = ch * GK_CHUNK;
        __syncthreads();   // previous chunk fully consumed
        // Load 4 tiles (xhi/xlo/whi/wlo), each 128 rows x 64 bf16, swizzled.
#pragma unroll
        for (int it = 0; it < 4; it++) {
            int e   = (it * 256 + tid) * 8;       // bf16 element index 0..8191
            int row = e >> 6;
            int col = e & 63;
            uint32_t swo = SWZ128((uint32_t)(row * 128 + col * 2));
            size_t xoff = (size_t)(n0 + row) * D_MODEL + k0 + col;
            size_t woff = (size_t)(m0 + row) * D_MODEL + k0 + col;
            *(uint4*)(sm + SO_XHI + swo) = *(const uint4*)&Xh[xoff];
            *(uint4*)(sm + SO_XLO + swo) = *(const uint4*)&Xl[xoff];
            *(uint4*)(sm + SO_WHI + swo) = *(const uint4*)&Wh[woff];
            *(uint4*)(sm + SO_WLO + swo) = *(const uint4*)&Wl[woff];
        }
        __syncthreads();

#pragma unroll
        for (int ks = 0; ks < 4; ks++) {
            const int kc = ks * 16;
            uint32_t ah[4][4], al[4][4];
#pragma unroll
            for (int mt = 0; mt < 4; mt++) {
                uint32_t off = SWZ128((uint32_t)((a_row + mt * 16) * 128 + (kc + a_kq) * 2));
                ldsm4(smem_base + SO_XHI + off, ah[mt]);
                ldsm4(smem_base + SO_XLO + off, al[mt]);
            }
            uint32_t bh[2][4], bl[2][4];
#pragma unroll
            for (int bt = 0; bt < 2; bt++) {
                uint32_t off = SWZ128((uint32_t)((b_row + bt * 16) * 128 + (kc + b_kq) * 2));
                ldsm4(smem_base + SO_WHI + off, bh[bt]);
                ldsm4(smem_base + SO_WLO + off, bl[bt]);
            }
#pragma unroll
            for (int mt = 0; mt < 4; mt++) {
#pragma unroll
                for (int nt = 0; nt < 4; nt++) {
                    int bt = nt >> 1, sb = (nt & 1) * 2;
                    mma16816(acc[mt][nt], ah[mt], bh[bt][sb], bh[bt][sb + 1]);
                    mma16816(acc[mt][nt], ah[mt], bl[bt][sb], bl[bt][sb + 1]);
                    mma16816(acc[mt][nt], al[mt], bh[bt][sb], bh[bt][sb + 1]);
                }
            }
        }
    }

    // Epilogue: stage fp32 tile in smem, then coalesced float4 stores.
    __syncthreads();
    float* dmat = (float*)sm;   // 128 x 132
    const int cr = lane >> 2;          // 0..7
    const int cc = (lane & 3) * 2;
#pragma unroll
    for (int mt = 0; mt < 4; mt++) {
#pragma unroll
        for (int nt = 0; nt < 4; nt++) {
            int r = wm * 64 + mt * 16 + cr;
            int c = wn * 32 + nt * 8 + cc;
            dmat[r * 132 + c]           = acc[mt][nt][0];
            dmat[r * 132 + c + 1]       = acc[mt][nt][1];
            dmat[(r + 8) * 132 + c]     = acc[mt][nt][2];
            dmat[(r + 8) * 132 + c + 1] = acc[mt][nt][3];
        }
    }
    __syncthreads();

    const int cq    = (tid & 15) * 4;
    const int rbase = tid >> 4;
#pragma unroll
    for (int rr = 0; rr < 8; rr++) {
        int r = rr * 16 + rbase;
        int n = n0 + r;
        int b = n >> 11;
        int s = n & (S_LEN - 1);
#pragma unroll
        for (int half = 0; half < 2; half++) {
            int head = (m0 >> 6) + half;
            float4 v = *(float4*)&dmat[r * 132 + half * 64 + cq];
            *(float4*)&out[(((size_t)(b * NHEADS + head) * S_LEN) + s) * HDIM + cq] = v;
        }
    }
}

// ---------------------------------------------------------------------------
// Kernel 2: flash attention with relative-position skew (UNCHANGED, proven)
// ---------------------------------------------------------------------------
#define SQ_OFF   0
#define SK_OFF   (65 * 65)
#define SV_OFF   (SK_OFF + 64 * 65)
#define SER_OFF  (SV_OFF + 64 * 65)
#define SP_OFF   (SER_OFF + 128 * 65)
#define SMEM_FLOATS (SP_OFF + 64 * 65)
#define SMEM_BYTES  (SMEM_FLOATS * 4)

__global__ __launch_bounds__(256) void attn_kernel(const float* __restrict__ Er)
{
    extern __shared__ float smf[];
    float* sq  = smf + SQ_OFF;
    float* sk  = smf + SK_OFF;
    float* sv  = smf + SV_OFF;
    float* ser = smf + SER_OFF;
    float* sp  = smf + SP_OFF;

    const int tid  = threadIdx.x;
    const int lane = tid & 31;
    const int wr   = tid >> 5;
    const int rl0  = wr * 8;
    const int s0   = blockIdx.x * 64;
    const int bh   = blockIdx.y;

    const float* qb = g_q + (size_t)bh * S_LEN * HDIM;
    const float* kb = g_k + (size_t)bh * S_LEN * HDIM;
    const float* vb = g_v + (size_t)bh * S_LEN * HDIM;

    for (int i4 = tid; i4 < 65 * 16; i4 += 256) {
        int r  = i4 >> 4;
        int kq = i4 & 15;
        float4 v = make_float4(0.f, 0.f, 0.f, 0.f);
        if (s0 + r < S_LEN) v = *(const float4*)&qb[(size_t)(s0 + r) * HDIM + kq * 4];
        float* dst = &sq[r * 65 + kq * 4];
        dst[0] = v.x; dst[1] = v.y; dst[2] = v.z; dst[3] = v.w;
    }

    float m_i[8], l_i[8], o_i[8][2];
#pragma unroll
    for (int r = 0; r < 8; r++) {
        m_i[r] = -1e30f; l_i[r] = 0.0f; o_i[r][0] = 0.0f; o_i[r][1] = 0.0f;
    }

    const float scale = 0.03125f;

    for (int t0 = 0; t0 < S_LEN; t0 += 64) {
        __syncthreads();

        for (int i4 = tid; i4 < 64 * 16; i4 += 256) {
            int c  = i4 >> 4;
            int kq = i4 & 15;
            float4 kv = *(const float4*)&kb[(size_t)(t0 + c) * HDIM + kq * 4];
            float* d1 = &sk[c * 65 + kq * 4];
            d1[0] = kv.x; d1[1] = kv.y; d1[2] = kv.z; d1[3] = kv.w;
            float4 vv = *(const float4*)&vb[(size_t)(t0 + c) * HDIM + kq * 4];
            float* d2 = &sv[c * 65 + kq * 4];
            d2[0] = vv.x; d2[1] = vv.y; d2[2] = vv.z; d2[3] = vv.w;
        }

        const int dlo = t0 - s0 - 63;
        for (int i4 = tid; i4 < 128 * 16; i4 += 256) {
            int di = i4 >> 4;
            int kq = i4 & 15;
            int d  = dlo + di;
            int j  = (d <= 0) ? (S_LEN - 1 + d) : (d - 2);
            float4 ev = make_float4(0.f, 0.f, 0.f, 0.f);
            if (j >= 0 && j < S_LEN) ev = *(const float4*)&Er[(size_t)j * HDIM + kq * 4];
            float* d3 = &ser[di * 65 + kq * 4];
            d3[0] = ev.x; d3[1] = ev.y; d3[2] = ev.z; d3[3] = ev.w;
        }
        __syncthreads();

        bool un[8][2];
#pragma unroll
        for (int r = 0; r < 8; r++) {
#pragma unroll
            for (int cc = 0; cc < 2; cc++) {
                int c = cc * 32 + lane;
                un[r][cc] = ((t0 + c) - (s0 + rl0 + r)) >= 2;
            }
        }

        float aqk[8][2], arl[8][2];
#pragma unroll
        for (int r = 0; r < 8; r++) {
            aqk[r][0] = 0.f; aqk[r][1] = 0.f; arl[r][0] = 0.f; arl[r][1] = 0.f;
        }

#pragma unroll 4
        for (int kk = 0; kk < HDIM; kk++) {
            float k0 = sk[lane * 65 + kk];
            float k1 = sk[(lane + 32) * 65 + kk];
            float qv[9];
#pragma unroll
            for (int r = 0; r < 9; r++) qv[r] = sq[(rl0 + r) * 65 + kk];
#pragma unroll
            for (int r = 0; r < 8; r++) {
                int diA = lane + 63 - (rl0 + r);
                float e0 = ser[diA * 65 + kk];
                float e1 = ser[(diA + 32) * 65 + kk];
                aqk[r][0] += qv[r] * k0;
                aqk[r][1] += qv[r] * k1;
                arl[r][0] += (un[r][0] ? qv[r + 1] : qv[r]) * e0;
                arl[r][1] += (un[r][1] ? qv[r + 1] : qv[r]) * e1;
            }
        }

#pragma unroll
        for (int r = 0; r < 8; r++) {
            float sc0 = (aqk[r][0] + arl[r][0]) * scale;
            float sc1 = (aqk[r][1] + arl[r][1]) * scale;
            float mx = fmaxf(sc0, sc1);
#pragma unroll
            for (int off = 16; off; off >>= 1)
                mx = fmaxf(mx, __shfl_xor_sync(0xffffffffu, mx, off));
            float mnew = fmaxf(m_i[r], mx);
            float p0 = __expf(sc0 - mnew);
            float p1 = __expf(sc1 - mnew);
            float ps = p0 + p1;
#pragma unroll
            for (int off = 16; off; off >>= 1)
                ps += __shfl_xor_sync(0xffffffffu, ps, off);
            float f = __expf(m_i[r] - mnew);
            l_i[r]  = l_i[r] * f + ps;
            m_i[r]  = mnew;
            o_i[r][0] *= f;
            o_i[r][1] *= f;
            sp[(rl0 + r) * 65 + lane]      = p0;
            sp[(rl0 + r) * 65 + lane + 32] = p1;
        }
        __syncwarp();

#pragma unroll 4
        for (int t = 0; t < 64; t++) {
            float v0 = sv[t * 65 + lane];
            float v1 = sv[t * 65 + lane + 32];
#pragma unroll
            for (int r = 0; r < 8; r++) {
                float pv = sp[(rl0 + r) * 65 + t];
                o_i[r][0] += pv * v0;
                o_i[r][1] += pv * v1;
            }
        }
    }

    const int b = bh >> 4;
    const int h = bh & 15;
#pragma unroll
    for (int r = 0; r < 8; r++) {
        int s = s0 + rl0 + r;
        float inv = 1.0f / l_i[r];
        float* op = &g_att[((size_t)(b * S_LEN + s)) * D_MODEL + h * HDIM];
        op[lane]      = o_i[r][0] * inv;
        op[lane + 32] = o_i[r][1] * inv;
    }
}

// ---------------------------------------------------------------------------
// Kernel 3: LayerNorm (unchanged)
// ---------------------------------------------------------------------------
__global__ __launch_bounds__(256) void ln_kernel(
    const float* __restrict__ lw, const float* __restrict__ lb,
    float* __restrict__ out)
{
    __shared__ float red[16];
    const int row = blockIdx.x;
    const int tid = threadIdx.x;
    const float* xr = g_att + (size_t)row * D_MODEL;

    float4 v = *(const float4*)&xr[tid * 4];
    float sum = v.x + v.y + v.z + v.w;
    float ss  = fmaf(v.x, v.x, fmaf(v.y, v.y, fmaf(v.z, v.z, v.w * v.w)));
#pragma unroll
    for (int off = 16; off; off >>= 1) {
        sum += __shfl_xor_sync(0xffffffffu, sum, off);
        ss  += __shfl_xor_sync(0xffffffffu, ss, off);
    }
    if ((tid & 31) == 0) {
        red[tid >> 5]       = sum;
        red[8 + (tid >> 5)] = ss;
    }
    __syncthreads();
    float ts = 0.f, tq = 0.f;
#pragma unroll
    for (int wv = 0; wv < 8; wv++) { ts += red[wv]; tq += red[8 + wv]; }
    float mu  = ts * (1.0f / D_MODEL);
    float var = tq * (1.0f / D_MODEL) - mu * mu;
    float rs  = rsqrtf(var + 1e-5f);

    float4 w4 = *(const float4*)&lw[tid * 4];
    float4 b4 = *(const float4*)&lb[tid * 4];
    float4 o;
    o.x = (v.x - mu) * rs * w4.x + b4.x;
    o.y = (v.y - mu) * rs * w4.y + b4.y;
    o.z = (v.z - mu) * rs * w4.z + b4.z;
    o.w = (v.w - mu) * rs * w4.w + b4.w;
    *(float4*)&out[(size_t)row * D_MODEL + tid * 4] = o;
}

// ---------------------------------------------------------------------------
extern "C" void kernel_launch(void* const* d_in, const int* in_sizes, int n_in,
                              void* d_out, int out_size)
{
    (void)in_sizes; (void)n_in; (void)out_size;
    const float* x  = (const float*)d_in[0];
    const float* Wq = (const float*)d_in[1];
    const float* Wk = (const float*)d_in[2];
    const float* Wv = (const float*)d_in[3];
    const float* Er = (const float*)d_in[4];
    const float* lw = (const float*)d_in[5];
    const float* lb = (const float*)d_in[6];
    float* out = (float*)d_out;

    split_kernel<<<(SPLIT_QUADS + 255) / 256, 256>>>(x, Wq, Wk, Wv);

    cudaFuncSetAttribute(qkv_mma_kernel,
                         cudaFuncAttributeMaxDynamicSharedMemorySize, GEMM_SMEM_BYTES);
    qkv_mma_kernel<<<dim3(D_MODEL / 128, NB * S_LEN / 128, 3), 256, GEMM_SMEM_BYTES>>>();

    cudaFuncSetAttribute(attn_kernel,
                         cudaFuncAttributeMaxDynamicSharedMemorySize, SMEM_BYTES);
    attn_kernel<<<dim3(S_LEN / 64, NB * NHEADS), 256, SMEM_BYTES>>>(Er);

    ln_kernel<<<NB * S_LEN, 256>>>(lw, lb, out);
}